// round 15
// baseline (speedup 1.0000x reference)
#include <cuda_runtime.h>
#include <cuda_bf16.h>
#include <stdint.h>

#define HEADS 8
#define TBL   3969   // 63*63

// ---------------- scratch (device globals; referenced ONLY in device code) ----------------
__device__ float g_tok[8192 * 256];
__device__ float g_qkv[8192 * 768];
__device__ float g_att[8192 * 256];
__device__ float g_wt [4096 * 256];     // unembed weight transposed [n'][c']
__device__ float g_wpT[256 * 256];      // proj weight transposed [c][c']
__device__ float g_wf [4096 * 256];     // fused proj+unembed weight [n'][c]
__device__ float g_bf [4096];           // fused bias per n'
__device__ float g_table[HEADS * TBL];

// ================= helpers =================
__device__ __forceinline__ uint32_t smem_u32(const void* p) {
    uint32_t a;
    asm("{ .reg .u64 t; cvta.to.shared.u64 t, %1; cvt.u32.u64 %0, t; }" : "=r"(a) : "l"(p));
    return a;
}
__device__ __forceinline__ void ldsm4(uint32_t* r, uint32_t addr) {
    asm volatile("ldmatrix.sync.aligned.m8n8.x4.shared.b16 {%0,%1,%2,%3}, [%4];"
        : "=r"(r[0]), "=r"(r[1]), "=r"(r[2]), "=r"(r[3]) : "r"(addr));
}
__device__ __forceinline__ void ldsm4t(uint32_t* r, uint32_t addr) {
    asm volatile("ldmatrix.sync.aligned.m8n8.x4.trans.shared.b16 {%0,%1,%2,%3}, [%4];"
        : "=r"(r[0]), "=r"(r[1]), "=r"(r[2]), "=r"(r[3]) : "r"(addr));
}
__device__ __forceinline__ void mma16816(float* d, const uint32_t* a, const uint32_t* b) {
    asm volatile("mma.sync.aligned.m16n8k16.row.col.f32.bf16.bf16.f32 "
        "{%0,%1,%2,%3}, {%4,%5,%6,%7}, {%8,%9}, {%0,%1,%2,%3};"
        : "+f"(d[0]), "+f"(d[1]), "+f"(d[2]), "+f"(d[3])
        : "r"(a[0]), "r"(a[1]), "r"(a[2]), "r"(a[3]), "r"(b[0]), "r"(b[1]));
}
__device__ __forceinline__ uint32_t packbf(float a, float b) {
    __nv_bfloat162 t = __halves2bfloat162(__float2bfloat16_rn(a), __float2bfloat16_rn(b));
    return *(uint32_t*)&t;
}
__device__ __forceinline__ void pack_hilo(float a, float b, uint32_t& hi, uint32_t& lo) {
    __nv_bfloat16 ha = __float2bfloat16_rn(a);
    __nv_bfloat16 hb = __float2bfloat16_rn(b);
    __nv_bfloat162 th = __halves2bfloat162(ha, hb);
    hi = *(uint32_t*)&th;
    lo = packbf(a - __bfloat162float(ha), b - __bfloat162float(hb));
}
__device__ __forceinline__ void cvt_store8(uint16_t* hiA, uint16_t* loA, int off,
                                           float4 v0, float4 v1) {
    float f[8] = {v0.x, v0.y, v0.z, v0.w, v1.x, v1.y, v1.z, v1.w};
    uint32_t h[4], l[4];
    #pragma unroll
    for (int i = 0; i < 4; i++) pack_hilo(f[2*i], f[2*i+1], h[i], l[i]);
    *(uint4*)&hiA[off] = *(uint4*)h;
    *(uint4*)&loA[off] = *(uint4*)l;
}
__device__ __forceinline__ void cvt_store4(uint16_t* hiA, uint16_t* loA, int off, float4 v) {
    uint32_t h[2], l[2];
    pack_hilo(v.x, v.y, h[0], l[0]);
    pack_hilo(v.z, v.w, h[1], l[1]);
    *(uint2*)&hiA[off] = *(uint2*)h;
    *(uint2*)&loA[off] = *(uint2*)l;
}

// ---------------- RPE MLP table ----------------
__global__ void rpe_kernel(const float* __restrict__ w1, const float* __restrict__ b1,
                           const float* __restrict__ w2) {
    __shared__ float sh[512];
    int e = blockIdx.x, tid = threadIdx.x;
    float rh = (float)((e / 63) - 31) * (1.0f / 31.0f);
    float rw = (float)((e % 63) - 31) * (1.0f / 31.0f);
    float r  = rh * w1[tid*2] + rw * w1[tid*2+1] + b1[tid];
    sh[tid]  = fmaxf(r, 0.0f);
    __syncthreads();
    int wid = tid >> 5, lane = tid & 31;
    if (wid < HEADS) {
        float s = 0.0f;
        for (int t = lane; t < 512; t += 32) s += sh[t] * w2[wid*512 + t];
        #pragma unroll
        for (int off = 16; off; off >>= 1) s += __shfl_xor_sync(0xffffffffu, s, off);
        if (lane == 0) g_table[wid*TBL + e] = s;
    }
}

// ---------------- transpose unembed weight: g_wt[n'][c'] = w[c'][n'] ----------------
__global__ void wt_kernel(const float* __restrict__ w) {
    __shared__ float t[32][33];
    int n0 = blockIdx.x * 32, c0 = blockIdx.y * 32;
    int tx = threadIdx.x, ty = threadIdx.y;
    #pragma unroll
    for (int r = 0; r < 4; r++)
        t[ty + 8*r][tx] = w[(c0 + ty + 8*r) * 4096 + n0 + tx];
    __syncthreads();
    #pragma unroll
    for (int r = 0; r < 4; r++)
        g_wt[(n0 + ty + 8*r) * 256 + c0 + tx] = t[tx][ty + 8*r];
}

// ---------------- transpose proj weight: g_wpT[c][c'] = w_proj[c'][c] ----------------
__global__ void wpT_kernel(const float* __restrict__ w) {
    __shared__ float t[32][33];
    int a0 = blockIdx.x * 32, b0 = blockIdx.y * 32;
    int tx = threadIdx.x, ty = threadIdx.y;
    #pragma unroll
    for (int r = 0; r < 4; r++)
        t[ty + 8*r][tx] = w[(b0 + ty + 8*r) * 256 + a0 + tx];
    __syncthreads();
    #pragma unroll
    for (int r = 0; r < 4; r++)
        g_wpT[(a0 + ty + 8*r) * 256 + b0 + tx] = t[tx][ty + 8*r];
}

// ---------------- fused bias ----------------
__global__ void bf_kernel(const float* __restrict__ bp, const float* __restrict__ bu) {
    int w = threadIdx.x >> 5, lane = threadIdx.x & 31;
    int np = blockIdx.x * 8 + w;
    float s = 0.0f;
    #pragma unroll
    for (int c = lane; c < 256; c += 32) s += bp[c] * g_wt[np * 256 + c];
    #pragma unroll
    for (int off = 16; off; off >>= 1) s += __shfl_xor_sync(0xffffffffu, s, off);
    if (lane == 0) g_bf[np] = s + bu[np >> 4];
}

// ================= generic bf16x3 GEMM (R14 verbatim) =================
#define SR 24
template<int NT>
__global__ __launch_bounds__(256, 2)
void mma_gemm(const float* __restrict__ Ag, const float* __restrict__ Bext,
              const float* __restrict__ bias, float* __restrict__ yout,
              int asel, int bdev, int csel, int K) {
    constexpr int NGRP = NT / 32;
    __shared__ __align__(16) uint16_t sAhi[2*128*SR];
    __shared__ __align__(16) uint16_t sAlo[2*128*SR];
    __shared__ __align__(16) uint16_t sBhi[2*NT*SR];
    __shared__ __align__(16) uint16_t sBlo[2*NT*SR];

    int tid = threadIdx.x, wid = tid >> 5, lane = tid & 31;
    int n0 = blockIdx.x * NT, m0 = blockIdx.y * 128;

    const float* A = asel == 1 ? g_tok : asel == 2 ? g_att : g_wt;
    const float* B = Bext ? Bext : (bdev == 2 ? g_wpT : g_wf);

    int lrow = tid >> 1, lkh = (tid & 1) * 8;
    const float* aG = A + (long)(m0 + lrow) * K + lkh;
    long astep = 16; int a2 = 4;
    int aoff = lrow * SR + lkh;

    const float* bG;
    int boff;
    if (NT == 128) { bG = B + (long)(n0 + lrow) * K + lkh;          boff = aoff; }
    else           { bG = B + (long)(n0 + (tid >> 2)) * K + (tid & 3) * 4;
                     boff = (tid >> 2) * SR + (tid & 3) * 4; }

    int wm = (wid >> 1) * 32, wn = (wid & 1) * (NT / 2);
    uint32_t aHiB = smem_u32(sAhi), aLoB = smem_u32(sAlo);
    uint32_t bHiB = smem_u32(sBhi), bLoB = smem_u32(sBlo);
    constexpr uint32_t ABUF = 128 * SR * 2, BBUF = NT * SR * 2;
    uint32_t aOff0 = ((wm + (lane & 15)) * SR + (lane >> 4) * 8) * 2;
    uint32_t aOff1 = aOff0 + 16 * SR * 2;
    int brow = wn + (lane & 7) + ((lane >> 4) << 3), bcol = lane & 8;
    uint32_t bOff[NGRP];
    #pragma unroll
    for (int g = 0; g < NGRP; g++) bOff[g] = ((brow + g*16) * SR + bcol) * 2;

    float acc[2][2*NGRP][4] = {};
    int nc = K / 16;

    float4 av0 = *(const float4*)(aG);
    float4 av1 = *(const float4*)(aG + a2);
    float4 bv0, bv1;
    if (NT == 128) { bv0 = *(const float4*)(bG); bv1 = *(const float4*)(bG + 4); }
    else           { bv0 = *(const float4*)(bG); }
    cvt_store8(sAhi, sAlo, aoff, av0, av1);
    if (NT == 128) cvt_store8(sBhi, sBlo, boff, bv0, bv1);
    else           cvt_store4(sBhi, sBlo, boff, bv0);
    av0 = *(const float4*)(aG + astep);
    av1 = *(const float4*)(aG + astep + a2);
    if (NT == 128) { bv0 = *(const float4*)(bG + 16); bv1 = *(const float4*)(bG + 20); }
    else           { bv0 = *(const float4*)(bG + 16); }

    for (int c = 0; c < nc; c++) {
        __syncthreads();
        uint32_t pa = (c & 1) * ABUF, pb = (c & 1) * BBUF;
        uint32_t ah[2][4], al[2][4], bh4[NGRP][4];
        uint32_t bl4[NGRP][4];
        ldsm4(ah[0], aHiB + pa + aOff0);
        ldsm4(ah[1], aHiB + pa + aOff1);
        ldsm4(al[0], aLoB + pa + aOff0);
        ldsm4(al[1], aLoB + pa + aOff1);
        #pragma unroll
        for (int g = 0; g < NGRP; g++) ldsm4(bh4[g], bHiB + pb + bOff[g]);
        if constexpr (NT == 64) {
            #pragma unroll
            for (int g = 0; g < NGRP; g++) ldsm4(bl4[g], bLoB + pb + bOff[g]);
        }

        if (c + 1 < nc) {
            int b1 = (c + 1) & 1;
            cvt_store8(sAhi + b1*(128*SR), sAlo + b1*(128*SR), aoff, av0, av1);
            if (NT == 128) cvt_store8(sBhi + b1*(NT*SR), sBlo + b1*(NT*SR), boff, bv0, bv1);
            else           cvt_store4(sBhi + b1*(NT*SR), sBlo + b1*(NT*SR), boff, bv0);
            if (c + 2 < nc) {
                av0 = *(const float4*)(aG + (long)(c+2)*astep);
                av1 = *(const float4*)(aG + (long)(c+2)*astep + a2);
                if (NT == 128) { bv0 = *(const float4*)(bG + (c+2)*16);
                                 bv1 = *(const float4*)(bG + (c+2)*16 + 4); }
                else           { bv0 = *(const float4*)(bG + (c+2)*16); }
            }
        }

        #pragma unroll
        for (int mf = 0; mf < 2; mf++)
            #pragma unroll
            for (int g = 0; g < NGRP; g++) {
                mma16816(acc[mf][g*2+0], ah[mf], &bh4[g][0]);
                mma16816(acc[mf][g*2+1], ah[mf], &bh4[g][2]);
            }
        #pragma unroll
        for (int mf = 0; mf < 2; mf++)
            #pragma unroll
            for (int g = 0; g < NGRP; g++) {
                mma16816(acc[mf][g*2+0], al[mf], &bh4[g][0]);
                mma16816(acc[mf][g*2+1], al[mf], &bh4[g][2]);
            }
        if constexpr (NT == 64) {
            #pragma unroll
            for (int mf = 0; mf < 2; mf++)
                #pragma unroll
                for (int g = 0; g < NGRP; g++) {
                    mma16816(acc[mf][g*2+0], ah[mf], &bl4[g][0]);
                    mma16816(acc[mf][g*2+1], ah[mf], &bl4[g][2]);
                }
        } else {
            #pragma unroll
            for (int g = 0; g < NGRP; g++) ldsm4(bh4[g], bLoB + pb + bOff[g]);
            #pragma unroll
            for (int mf = 0; mf < 2; mf++)
                #pragma unroll
                for (int g = 0; g < NGRP; g++) {
                    mma16816(acc[mf][g*2+0], ah[mf], &bh4[g][0]);
                    mma16816(acc[mf][g*2+1], ah[mf], &bh4[g][2]);
                }
        }
    }

    int r0 = m0 + wm + (lane >> 2);
    int nb = n0 + wn + (lane & 3) * 2;
    #pragma unroll
    for (int mf = 0; mf < 2; mf++) {
        int r = r0 + mf * 16;
        #pragma unroll
        for (int nf = 0; nf < 2*NGRP; nf++) {
            int n = nb + nf * 8;
            float* d = acc[mf][nf];
            if (csel <= 1) {
                float* C = csel == 0 ? g_tok : g_qkv;
                int ldc = (csel == 1) ? 768 : 256;
                float b0 = __ldg(&bias[n]), b1 = __ldg(&bias[n+1]);
                float2 lo2 = {d[0] + b0, d[1] + b1};
                float2 hi2 = {d[2] + b0, d[3] + b1};
                *(float2*)&C[(long)r * ldc + n]       = lo2;
                *(float2*)&C[(long)(r + 8) * ldc + n] = hi2;
            } else if (csel == 4) {
                float2 lo2 = {d[0], d[1]};
                float2 hi2 = {d[2], d[3]};
                *(float2*)&g_wf[(long)r * 256 + n]       = lo2;
                *(float2*)&g_wf[(long)(r + 8) * 256 + n] = hi2;
            } else {
                int o = n >> 4, p = (n >> 2) & 3, q = n & 3;
                float b0 = g_bf[n], b1 = g_bf[n + 1];
                int bb = r >> 10, hp = (r >> 5) & 31, wp = r & 31;
                float2 lo2 = {d[0] + b0, d[1] + b1};
                *(float2*)&yout[((long)(bb*256 + o)*128 + hp*4 + p)*128 + wp*4 + q] = lo2;
                int r8 = r + 8;
                int b2 = r8 >> 10, hp2 = (r8 >> 5) & 31, wp2 = r8 & 31;
                float2 hi2 = {d[2] + b0, d[3] + b1};
                *(float2*)&yout[((long)(b2*256 + o)*128 + hp2*4 + p)*128 + wp2*4 + q] = hi2;
            }
        }
    }
}

// ================= embed GEMM: K-chunk 32, dynamic smem (60KB) =================
// tok[m, n] = gather(x)[m, k] * w_embed[n, k]^T + b_embed, M=8192, N=256(tiles of 64), K=4096
#define SR2 40
__global__ __launch_bounds__(256, 2)
void embed32_kernel(const float* __restrict__ x, const float* __restrict__ w,
                    const float* __restrict__ bias) {
    extern __shared__ __align__(16) uint16_t dsm[];
    uint16_t* sAhi = dsm;                    // 2 * 128 * 40
    uint16_t* sAlo = dsm + 10240;
    uint16_t* sBhi = dsm + 20480;            // 2 * 64 * 40
    uint16_t* sBlo = dsm + 25600;

    int tid = threadIdx.x, wid = tid >> 5, lane = tid & 31;
    int n0 = blockIdx.x * 64, m0 = blockIdx.y * 128;

    // A gather: thread -> row lrow, k-sub kh16 = (tid&1)*16 (one channel, 4 pixel rows)
    int lrow = tid >> 1, kh16 = (tid & 1) * 16;
    int m = m0 + lrow;
    int bb = m >> 10, hp = (m >> 5) & 31, wp = m & 31;
    const float* aG = x + ((long)bb * 256 * 128 + hp * 4) * 128 + wp * 4;  // c=0,p=0
    int aoff = lrow * SR2 + kh16;

    // B: thread -> row tid>>2, k8 = (tid&3)*8
    int browL = tid >> 2, bk8 = (tid & 3) * 8;
    const float* bG = w + (long)(n0 + browL) * 4096 + bk8;
    int boff = browL * SR2 + bk8;

    int wm = (wid >> 1) * 32, wn = (wid & 1) * 32;
    uint32_t aHiB = smem_u32(sAhi), aLoB = smem_u32(sAlo);
    uint32_t bHiB = smem_u32(sBhi), bLoB = smem_u32(sBlo);
    constexpr uint32_t ABUF = 128 * SR2 * 2, BBUF = 64 * SR2 * 2;
    uint32_t aOff0 = ((wm + (lane & 15)) * SR2 + (lane >> 4) * 8) * 2;
    uint32_t aOff1 = aOff0 + 16 * SR2 * 2;
    int brow = wn + (lane & 7) + ((lane >> 4) << 3), bcol = lane & 8;
    uint32_t bOff[2];
    #pragma unroll
    for (int g = 0; g < 2; g++) bOff[g] = ((brow + g*16) * SR2 + bcol) * 2;

    float acc[2][4][4] = {};
    const int nc = 128;   // 4096 / 32

    // prefetch helpers: chunk c -> channel ch = 2c + (tid&1); 4 float4 at pixel rows p=0..3
    float4 pv[4]; float4 bv0, bv1;
    {
        long ao = (long)(tid & 1) * 16384;
        #pragma unroll
        for (int p = 0; p < 4; p++) pv[p] = *(const float4*)(aG + ao + p * 128);
        bv0 = *(const float4*)(bG);
        bv1 = *(const float4*)(bG + 4);
    }
    // store chunk 0 -> buffer 0
    cvt_store8(sAhi, sAlo, aoff,     pv[0], pv[1]);
    cvt_store8(sAhi, sAlo, aoff + 8, pv[2], pv[3]);
    cvt_store8(sBhi, sBlo, boff, bv0, bv1);
    // prefetch chunk 1
    {
        long ao = (long)(2 + (tid & 1)) * 16384;
        #pragma unroll
        for (int p = 0; p < 4; p++) pv[p] = *(const float4*)(aG + ao + p * 128);
        bv0 = *(const float4*)(bG + 32);
        bv1 = *(const float4*)(bG + 36);
    }

    for (int c = 0; c < nc; c++) {
        __syncthreads();
        uint32_t pa = (c & 1) * ABUF, pb = (c & 1) * BBUF;

        // ---- dc = 0 ----
        uint32_t ah[2][4], al[2][4], b4[2][4];
        ldsm4(ah[0], aHiB + pa + aOff0);
        ldsm4(ah[1], aHiB + pa + aOff1);
        ldsm4(al[0], aLoB + pa + aOff0);
        ldsm4(al[1], aLoB + pa + aOff1);
        ldsm4(b4[0], bHiB + pb + bOff[0]);
        ldsm4(b4[1], bHiB + pb + bOff[1]);

        // store chunk c+1 -> other buffer; prefetch c+2
        if (c + 1 < nc) {
            int b1 = (c + 1) & 1;
            cvt_store8(sAhi + b1*(128*SR2), sAlo + b1*(128*SR2), aoff,     pv[0], pv[1]);
            cvt_store8(sAhi + b1*(128*SR2), sAlo + b1*(128*SR2), aoff + 8, pv[2], pv[3]);
            cvt_store8(sBhi + b1*(64*SR2),  sBlo + b1*(64*SR2),  boff, bv0, bv1);
            if (c + 2 < nc) {
                long ao = (long)(2*(c+2) + (tid & 1)) * 16384;
                #pragma unroll
                for (int p = 0; p < 4; p++) pv[p] = *(const float4*)(aG + ao + p * 128);
                bv0 = *(const float4*)(bG + (c+2)*32);
                bv1 = *(const float4*)(bG + (c+2)*32 + 4);
            }
        }

        #pragma unroll
        for (int dc = 0; dc < 2; dc++) {
            uint32_t kadj = dc * 32;   // +16 elements * 2 bytes
            if (dc == 1) {
                ldsm4(ah[0], aHiB + pa + aOff0 + kadj);
                ldsm4(ah[1], aHiB + pa + aOff1 + kadj);
                ldsm4(al[0], aLoB + pa + aOff0 + kadj);
                ldsm4(al[1], aLoB + pa + aOff1 + kadj);
                ldsm4(b4[0], bHiB + pb + bOff[0] + kadj);
                ldsm4(b4[1], bHiB + pb + bOff[1] + kadj);
            }
            // pass1: Ahi*Bhi
            #pragma unroll
            for (int mf = 0; mf < 2; mf++)
                #pragma unroll
                for (int g = 0; g < 2; g++) {
                    mma16816(acc[mf][g*2+0], ah[mf], &b4[g][0]);
                    mma16816(acc[mf][g*2+1], ah[mf], &b4[g][2]);
                }
            // pass2: Alo*Bhi
            #pragma unroll
            for (int mf = 0; mf < 2; mf++)
                #pragma unroll
                for (int g = 0; g < 2; g++) {
                    mma16816(acc[mf][g*2+0], al[mf], &b4[g][0]);
                    mma16816(acc[mf][g*2+1], al[mf], &b4[g][2]);
                }
            // pass3: Ahi*Blo
            ldsm4(b4[0], bLoB + pb + bOff[0] + kadj);
            ldsm4(b4[1], bLoB + pb + bOff[1] + kadj);
            #pragma unroll
            for (int mf = 0; mf < 2; mf++)
                #pragma unroll
                for (int g = 0; g < 2; g++) {
                    mma16816(acc[mf][g*2+0], ah[mf], &b4[g][0]);
                    mma16816(acc[mf][g*2+1], ah[mf], &b4[g][2]);
                }
        }
    }

    // ---- epilogue -> g_tok + bias ----
    int r0 = m0 + wm + (lane >> 2);
    int nb = n0 + wn + (lane & 3) * 2;
    #pragma unroll
    for (int mf = 0; mf < 2; mf++) {
        int r = r0 + mf * 16;
        #pragma unroll
        for (int nf = 0; nf < 4; nf++) {
            int n = nb + nf * 8;
            float* d = acc[mf][nf];
            float b0 = __ldg(&bias[n]), b1 = __ldg(&bias[n+1]);
            float2 lo2 = {d[0] + b0, d[1] + b1};
            float2 hi2 = {d[2] + b0, d[3] + b1};
            *(float2*)&g_tok[(long)r * 256 + n]       = lo2;
            *(float2*)&g_tok[(long)(r + 8) * 256 + n] = hi2;
        }
    }
}

// ================= tensor-core flash attention (R11/R14 verbatim) =================
__global__ __launch_bounds__(256, 2)
void attn_mma_kernel() {
    __shared__ __align__(16) uint16_t sKhi[2*2560];
    __shared__ __align__(16) uint16_t sKlo[2*2560];
    __shared__ __align__(16) uint16_t sVhi[2*2560];
    __shared__ __align__(16) uint16_t sVlo[2*2560];

    int tid = threadIdx.x, w = tid >> 5, lane = tid & 31;
    int bx = blockIdx.x, qs = bx & 7, bh = bx >> 3;
    int b = bh >> 3, h = bh & 7;
    int q0 = qs * 128;
    uint32_t kHB = smem_u32(sKhi), kLB = smem_u32(sKlo);
    uint32_t vHB = smem_u32(sVhi), vLB = smem_u32(sVlo);

    int kvrow = tid >> 2, kvdg = (tid & 3) * 8;
    const float* kv0 = &g_qkv[((b << 10) + kvrow) * 768 + h * 32 + kvdg];
    float4 ka = *(const float4*)(kv0 + 256);
    float4 kb = *(const float4*)(kv0 + 260);
    float4 va = *(const float4*)(kv0 + 512);
    float4 vb = *(const float4*)(kv0 + 516);

    {
        int row = tid >> 1;
        const float* qp = &g_qkv[((b << 10) + q0 + row) * 768 + h * 32];
        #pragma unroll
        for (int it = 0; it < 2; it++) {
            int d0 = (tid & 1) * 8 + it * 16;
            float4 v0 = *(const float4*)(qp + d0);
            float4 v1 = *(const float4*)(qp + d0 + 4);
            const float S = 0.17677669529663687f;
            v0.x *= S; v0.y *= S; v0.z *= S; v0.w *= S;
            v1.x *= S; v1.y *= S; v1.z *= S; v1.w *= S;
            cvt_store8(sKhi, sKlo, row * 40 + d0, v0, v1);
        }
    }
    __syncthreads();
    uint32_t qh[2][4], ql[2][4];
    {
        uint32_t qa = ((w * 16 + (lane & 15)) * 40 + (lane >> 4) * 8) * 2;
        #pragma unroll
        for (int dc = 0; dc < 2; dc++) {
            ldsm4(qh[dc], kHB + qa + dc * 32);
            ldsm4(ql[dc], kLB + qa + dc * 32);
        }
    }
    __syncthreads();

    int soff = kvrow * 40 + kvdg;
    cvt_store8(sKhi, sKlo, soff, ka, kb);
    cvt_store8(sVhi, sVlo, soff, va, vb);
    ka = *(const float4*)(kv0 + 49152 + 256);
    kb = *(const float4*)(kv0 + 49152 + 260);
    va = *(const float4*)(kv0 + 49152 + 512);
    vb = *(const float4*)(kv0 + 49152 + 516);

    uint32_t kOff = (((lane & 7) + ((lane >> 4) << 3)) * 40 + (lane & 8)) * 2;
    uint32_t vOff = ((lane & 15) * 40 + (lane >> 4) * 8) * 2;

    int nq0 = q0 + w * 16 + (lane >> 2), nq1 = nq0 + 8;
    int bi0 = ((nq0 >> 5) + 31) * 63 + (nq0 & 31) + 31;
    int bi1 = ((nq1 >> 5) + 31) * 63 + (nq1 & 31) + 31;
    const float* tab = g_table + h * TBL;

    float m0r = -1e30f, m1r = -1e30f, l0 = 0.0f, l1 = 0.0f;
    float O[4][4] = {};

    for (int t = 0; t < 16; t++) {
        __syncthreads();
        uint32_t pk = (t & 1) * 5120;

        float sc[8][4] = {};
        #pragma unroll
        for (int dc = 0; dc < 2; dc++) {
            #pragma unroll
            for (int nfp = 0; nfp < 4; nfp++) {
                uint32_t off = (nfp * 640 + dc * 16) * 2;
                uint32_t b4[4];
                ldsm4(b4, kHB + pk + kOff + off);
                mma16816(sc[2*nfp],   qh[dc], &b4[0]);
                mma16816(sc[2*nfp+1], qh[dc], &b4[2]);
                mma16816(sc[2*nfp],   ql[dc], &b4[0]);
                mma16816(sc[2*nfp+1], ql[dc], &b4[2]);
                ldsm4(b4, kLB + pk + kOff + off);
                mma16816(sc[2*nfp],   qh[dc], &b4[0]);
                mma16816(sc[2*nfp+1], qh[dc], &b4[2]);
            }
        }

        if (t + 1 < 16) {
            int d = ((t + 1) & 1) * 2560 + soff;
            cvt_store8(sKhi, sKlo, d, ka, kb);
            cvt_store8(sVhi, sVlo, d, va, vb);
            if (t + 2 < 16) {
                const float* s = kv0 + (long)(t + 2) * 49152;
                ka = *(const float4*)(s + 256);
                kb = *(const float4*)(s + 260);
                va = *(const float4*)(s + 512);
                vb = *(const float4*)(s + 516);
            }
        }

        int tb = t * 126;
        #pragma unroll
        for (int nf = 0; nf < 8; nf++) {
            int cb = (nf >> 2) * 63 + (nf & 3) * 8 + (lane & 3) * 2;
            sc[nf][0] += __ldg(&tab[bi0 - tb - cb]);
            sc[nf][1] += __ldg(&tab[bi0 - tb - cb - 1]);
            sc[nf][2] += __ldg(&tab[bi1 - tb - cb]);
            sc[nf][3] += __ldg(&tab[bi1 - tb - cb - 1]);
        }

        float mx0 = -1e30f, mx1 = -1e30f;
        #pragma unroll
        for (int nf = 0; nf < 8; nf++) {
            mx0 = fmaxf(mx0, fmaxf(sc[nf][0], sc[nf][1]));
            mx1 = fmaxf(mx1, fmaxf(sc[nf][2], sc[nf][3]));
        }
        #pragma unroll
        for (int off = 1; off < 4; off <<= 1) {
            mx0 = fmaxf(mx0, __shfl_xor_sync(0xffffffffu, mx0, off));
            mx1 = fmaxf(mx1, __shfl_xor_sync(0xffffffffu, mx1, off));
        }
        float mn0 = fmaxf(m0r, mx0), mn1 = fmaxf(m1r, mx1);
        float s0 = __expf(m0r - mn0), s1 = __expf(m1r - mn1);
        m0r = mn0; m1r = mn1;

        float ps0 = 0.0f, ps1 = 0.0f;
        #pragma unroll
        for (int nf = 0; nf < 8; nf++) {
            float p0 = __expf(sc[nf][0] - mn0);
            float p1 = __expf(sc[nf][1] - mn0);
            float p2 = __expf(sc[nf][2] - mn1);
            float p3 = __expf(sc[nf][3] - mn1);
            ps0 += p0 + p1; ps1 += p2 + p3;
            sc[nf][0] = p0; sc[nf][1] = p1; sc[nf][2] = p2; sc[nf][3] = p3;
        }
        #pragma unroll
        for (int off = 1; off < 4; off <<= 1) {
            ps0 += __shfl_xor_sync(0xffffffffu, ps0, off);
            ps1 += __shfl_xor_sync(0xffffffffu, ps1, off);
        }
        l0 = l0 * s0 + ps0;
        l1 = l1 * s1 + ps1;
        #pragma unroll
        for (int nf = 0; nf < 4; nf++) {
            O[nf][0] *= s0; O[nf][1] *= s0;
            O[nf][2] *= s1; O[nf][3] *= s1;
        }

        #pragma unroll
        for (int kc = 0; kc < 4; kc++) {
            uint32_t ph[4], pl[4];
            pack_hilo(sc[2*kc][0],   sc[2*kc][1],   ph[0], pl[0]);
            pack_hilo(sc[2*kc][2],   sc[2*kc][3],   ph[1], pl[1]);
            pack_hilo(sc[2*kc+1][0], sc[2*kc+1][1], ph[2], pl[2]);
            pack_hilo(sc[2*kc+1][2], sc[2*kc+1][3], ph[3], pl[3]);
            #pragma unroll
            for (int dfp = 0; dfp < 2; dfp++) {
                uint32_t off = (kc * 640 + dfp * 16) * 2;
                uint32_t b4[4];
                ldsm4t(b4, vHB + pk + vOff + off);
                mma16816(O[2*dfp],   ph, &b4[0]);
                mma16816(O[2*dfp+1], ph, &b4[2]);
                mma16816(O[2*dfp],   pl, &b4[0]);
                mma16816(O[2*dfp+1], pl, &b4[2]);
                ldsm4t(b4, vLB + pk + vOff + off);
                mma16816(O[2*dfp],   ph, &b4[0]);
                mma16816(O[2*dfp+1], ph, &b4[2]);
            }
        }
    }

    float i0 = 1.0f / l0, i1 = 1.0f / l1;
    #pragma unroll
    for (int nf = 0; nf < 4; nf++) {
        int d = h * 32 + nf * 8 + (lane & 3) * 2;
        float2 o0 = {O[nf][0] * i0, O[nf][1] * i0};
        float2 o1 = {O[nf][2] * i1, O[nf][3] * i1};
        *(float2*)&g_att[((b << 10) + nq0) * 256 + d] = o0;
        *(float2*)&g_att[((b << 10) + nq1) * 256 + d] = o1;
    }
}

// ---------------- launch ----------------
extern "C" void kernel_launch(void* const* d_in, const int* in_sizes, int n_in,
                              void* d_out, int out_size) {
    const float* x         = (const float*)d_in[0];
    const float* w_embed   = (const float*)d_in[1];
    const float* b_embed   = (const float*)d_in[2];
    const float* cpb_w1    = (const float*)d_in[3];
    const float* cpb_b1    = (const float*)d_in[4];
    const float* cpb_w2    = (const float*)d_in[5];
    const float* w_qkv     = (const float*)d_in[6];
    const float* b_qkv     = (const float*)d_in[7];
    const float* w_proj    = (const float*)d_in[8];
    const float* b_proj    = (const float*)d_in[9];
    const float* w_unembed = (const float*)d_in[10];
    const float* b_unembed = (const float*)d_in[11];
    float* y = (float*)d_out;

    cudaFuncSetAttribute(embed32_kernel,
                         cudaFuncAttributeMaxDynamicSharedMemorySize, 61440);

    rpe_kernel<<<TBL, 512>>>(cpb_w1, cpb_b1, cpb_w2);
    wt_kernel <<<dim3(128, 8), dim3(32, 8)>>>(w_unembed);
    wpT_kernel<<<dim3(8, 8),   dim3(32, 8)>>>(w_proj);
    mma_gemm<64> <<<dim3(4, 32),  256>>>(nullptr, nullptr, nullptr, nullptr, 4, 2, 4, 256);
    bf_kernel <<<512, 256>>>(b_proj, b_unembed);
    // embed: KC=32, dynamic smem
    embed32_kernel<<<dim3(4, 64), 256, 61440>>>(x, w_embed, b_embed);
    // qkv
    mma_gemm<128><<<dim3(6, 64),  256>>>(nullptr, w_qkv, b_qkv, nullptr, 1, 0, 1, 256);
    attn_mma_kernel<<<512, 256>>>();
    // fused proj+unembed
    mma_gemm<128><<<dim3(32, 64), 256>>>(nullptr, nullptr, nullptr, y, 2, 3, 3, 256);
}

// round 16
// speedup vs baseline: 1.0152x; 1.0152x over previous
#include <cuda_runtime.h>
#include <cuda_bf16.h>
#include <stdint.h>

#define HEADS 8
#define TBL   3969   // 63*63

// ---------------- scratch (device globals; referenced ONLY in device code) ----------------
__device__ float g_tok[8192 * 256];
__device__ float g_qkv[8192 * 768];
__device__ float g_att[8192 * 256];
__device__ float g_wt [4096 * 256];     // unembed weight transposed [n'][c']
__device__ float g_wpT[256 * 256];      // proj weight transposed [c][c']
__device__ float g_wf [4096 * 256];     // fused proj+unembed weight [n'][c]
__device__ float g_bf [4096];           // fused bias per n'
__device__ float g_table[HEADS * TBL];

// ================= helpers =================
__device__ __forceinline__ uint32_t smem_u32(const void* p) {
    uint32_t a;
    asm("{ .reg .u64 t; cvta.to.shared.u64 t, %1; cvt.u32.u64 %0, t; }" : "=r"(a) : "l"(p));
    return a;
}
__device__ __forceinline__ void ldsm4(uint32_t* r, uint32_t addr) {
    asm volatile("ldmatrix.sync.aligned.m8n8.x4.shared.b16 {%0,%1,%2,%3}, [%4];"
        : "=r"(r[0]), "=r"(r[1]), "=r"(r[2]), "=r"(r[3]) : "r"(addr));
}
__device__ __forceinline__ void ldsm4t(uint32_t* r, uint32_t addr) {
    asm volatile("ldmatrix.sync.aligned.m8n8.x4.trans.shared.b16 {%0,%1,%2,%3}, [%4];"
        : "=r"(r[0]), "=r"(r[1]), "=r"(r[2]), "=r"(r[3]) : "r"(addr));
}
__device__ __forceinline__ void mma16816(float* d, const uint32_t* a, const uint32_t* b) {
    asm volatile("mma.sync.aligned.m16n8k16.row.col.f32.bf16.bf16.f32 "
        "{%0,%1,%2,%3}, {%4,%5,%6,%7}, {%8,%9}, {%0,%1,%2,%3};"
        : "+f"(d[0]), "+f"(d[1]), "+f"(d[2]), "+f"(d[3])
        : "r"(a[0]), "r"(a[1]), "r"(a[2]), "r"(a[3]), "r"(b[0]), "r"(b[1]));
}
__device__ __forceinline__ uint32_t packbf(float a, float b) {
    __nv_bfloat162 t = __halves2bfloat162(__float2bfloat16_rn(a), __float2bfloat16_rn(b));
    return *(uint32_t*)&t;
}
__device__ __forceinline__ void pack_hilo(float a, float b, uint32_t& hi, uint32_t& lo) {
    __nv_bfloat16 ha = __float2bfloat16_rn(a);
    __nv_bfloat16 hb = __float2bfloat16_rn(b);
    __nv_bfloat162 th = __halves2bfloat162(ha, hb);
    hi = *(uint32_t*)&th;
    lo = packbf(a - __bfloat162float(ha), b - __bfloat162float(hb));
}
__device__ __forceinline__ void cvt_store8(uint16_t* hiA, uint16_t* loA, int off,
                                           float4 v0, float4 v1) {
    float f[8] = {v0.x, v0.y, v0.z, v0.w, v1.x, v1.y, v1.z, v1.w};
    uint32_t h[4], l[4];
    #pragma unroll
    for (int i = 0; i < 4; i++) pack_hilo(f[2*i], f[2*i+1], h[i], l[i]);
    *(uint4*)&hiA[off] = *(uint4*)h;
    *(uint4*)&loA[off] = *(uint4*)l;
}
__device__ __forceinline__ void cvt_store4(uint16_t* hiA, uint16_t* loA, int off, float4 v) {
    uint32_t h[2], l[2];
    pack_hilo(v.x, v.y, h[0], l[0]);
    pack_hilo(v.z, v.w, h[1], l[1]);
    *(uint2*)&hiA[off] = *(uint2*)h;
    *(uint2*)&loA[off] = *(uint2*)l;
}

// ---------------- RPE MLP table ----------------
__global__ void rpe_kernel(const float* __restrict__ w1, const float* __restrict__ b1,
                           const float* __restrict__ w2) {
    __shared__ float sh[512];
    int e = blockIdx.x, tid = threadIdx.x;
    float rh = (float)((e / 63) - 31) * (1.0f / 31.0f);
    float rw = (float)((e % 63) - 31) * (1.0f / 31.0f);
    float r  = rh * w1[tid*2] + rw * w1[tid*2+1] + b1[tid];
    sh[tid]  = fmaxf(r, 0.0f);
    __syncthreads();
    int wid = tid >> 5, lane = tid & 31;
    if (wid < HEADS) {
        float s = 0.0f;
        for (int t = lane; t < 512; t += 32) s += sh[t] * w2[wid*512 + t];
        #pragma unroll
        for (int off = 16; off; off >>= 1) s += __shfl_xor_sync(0xffffffffu, s, off);
        if (lane == 0) g_table[wid*TBL + e] = s;
    }
}

// ---------------- transpose unembed weight: g_wt[n'][c'] = w[c'][n'] ----------------
__global__ void wt_kernel(const float* __restrict__ w) {
    __shared__ float t[32][33];
    int n0 = blockIdx.x * 32, c0 = blockIdx.y * 32;
    int tx = threadIdx.x, ty = threadIdx.y;
    #pragma unroll
    for (int r = 0; r < 4; r++)
        t[ty + 8*r][tx] = w[(c0 + ty + 8*r) * 4096 + n0 + tx];
    __syncthreads();
    #pragma unroll
    for (int r = 0; r < 4; r++)
        g_wt[(n0 + ty + 8*r) * 256 + c0 + tx] = t[tx][ty + 8*r];
}

// ---------------- transpose proj weight: g_wpT[c][c'] = w_proj[c'][c] ----------------
__global__ void wpT_kernel(const float* __restrict__ w) {
    __shared__ float t[32][33];
    int a0 = blockIdx.x * 32, b0 = blockIdx.y * 32;
    int tx = threadIdx.x, ty = threadIdx.y;
    #pragma unroll
    for (int r = 0; r < 4; r++)
        t[ty + 8*r][tx] = w[(b0 + ty + 8*r) * 256 + a0 + tx];
    __syncthreads();
    #pragma unroll
    for (int r = 0; r < 4; r++)
        g_wpT[(a0 + ty + 8*r) * 256 + b0 + tx] = t[tx][ty + 8*r];
}

// ---------------- fused bias ----------------
__global__ void bf_kernel(const float* __restrict__ bp, const float* __restrict__ bu) {
    int w = threadIdx.x >> 5, lane = threadIdx.x & 31;
    int np = blockIdx.x * 8 + w;
    float s = 0.0f;
    #pragma unroll
    for (int c = lane; c < 256; c += 32) s += bp[c] * g_wt[np * 256 + c];
    #pragma unroll
    for (int off = 16; off; off >>= 1) s += __shfl_xor_sync(0xffffffffu, s, off);
    if (lane == 0) g_bf[np] = s + bu[np >> 4];
}

// ================= bf16x3 tensor-core GEMM (R14 verbatim) =================
// asel: 0=gather(x), 1=g_tok, 2=g_att, 4=g_wt
// B: Bext if nonnull, else bdev: 2=g_wpT, 3=g_wf
// csel: 0->g_tok, 1->g_qkv, 3->scatter y with g_bf, 4->g_wf (no bias)
#define SR 24
template<int NT>
__global__ __launch_bounds__(256, 2)
void mma_gemm(const float* __restrict__ Ag, const float* __restrict__ Bext,
              const float* __restrict__ bias, float* __restrict__ yout,
              int asel, int bdev, int csel, int K) {
    constexpr int NGRP = NT / 32;
    __shared__ __align__(16) uint16_t sAhi[2*128*SR];
    __shared__ __align__(16) uint16_t sAlo[2*128*SR];
    __shared__ __align__(16) uint16_t sBhi[2*NT*SR];
    __shared__ __align__(16) uint16_t sBlo[2*NT*SR];

    int tid = threadIdx.x, wid = tid >> 5, lane = tid & 31;
    int n0 = blockIdx.x * NT, m0 = blockIdx.y * 128;

    const float* A = asel == 1 ? g_tok : asel == 2 ? g_att : g_wt;
    const float* B = Bext ? Bext : (bdev == 2 ? g_wpT : g_wf);

    int lrow = tid >> 1, lkh = (tid & 1) * 8;
    const float* aG;
    long astep; int a2;
    if (asel == 0) {
        int m = m0 + lrow;
        int bb = m >> 10, hp = (m >> 5) & 31, wp = m & 31;
        int p = lkh >> 2;
        aG = Ag + (long)bb * (256*16384) + (hp*4 + p) * 128 + wp * 4;
        astep = 16384; a2 = 128;
    } else {
        aG = A + (long)(m0 + lrow) * K + lkh;
        astep = 16; a2 = 4;
    }
    int aoff = lrow * SR + lkh;

    const float* bG;
    int boff;
    if (NT == 128) { bG = B + (long)(n0 + lrow) * K + lkh;          boff = aoff; }
    else           { bG = B + (long)(n0 + (tid >> 2)) * K + (tid & 3) * 4;
                     boff = (tid >> 2) * SR + (tid & 3) * 4; }

    int wm = (wid >> 1) * 32, wn = (wid & 1) * (NT / 2);
    uint32_t aHiB = smem_u32(sAhi), aLoB = smem_u32(sAlo);
    uint32_t bHiB = smem_u32(sBhi), bLoB = smem_u32(sBlo);
    constexpr uint32_t ABUF = 128 * SR * 2, BBUF = NT * SR * 2;
    uint32_t aOff0 = ((wm + (lane & 15)) * SR + (lane >> 4) * 8) * 2;
    uint32_t aOff1 = aOff0 + 16 * SR * 2;
    int brow = wn + (lane & 7) + ((lane >> 4) << 3), bcol = lane & 8;
    uint32_t bOff[NGRP];
    #pragma unroll
    for (int g = 0; g < NGRP; g++) bOff[g] = ((brow + g*16) * SR + bcol) * 2;

    float acc[2][2*NGRP][4] = {};
    int nc = K / 16;

    float4 av0 = *(const float4*)(aG);
    float4 av1 = *(const float4*)(aG + a2);
    float4 bv0, bv1;
    if (NT == 128) { bv0 = *(const float4*)(bG); bv1 = *(const float4*)(bG + 4); }
    else           { bv0 = *(const float4*)(bG); }
    cvt_store8(sAhi, sAlo, aoff, av0, av1);
    if (NT == 128) cvt_store8(sBhi, sBlo, boff, bv0, bv1);
    else           cvt_store4(sBhi, sBlo, boff, bv0);
    av0 = *(const float4*)(aG + astep);
    av1 = *(const float4*)(aG + astep + a2);
    if (NT == 128) { bv0 = *(const float4*)(bG + 16); bv1 = *(const float4*)(bG + 20); }
    else           { bv0 = *(const float4*)(bG + 16); }

    for (int c = 0; c < nc; c++) {
        __syncthreads();
        uint32_t pa = (c & 1) * ABUF, pb = (c & 1) * BBUF;
        uint32_t ah[2][4], al[2][4], bh4[NGRP][4];
        uint32_t bl4[NGRP][4];
        ldsm4(ah[0], aHiB + pa + aOff0);
        ldsm4(ah[1], aHiB + pa + aOff1);
        ldsm4(al[0], aLoB + pa + aOff0);
        ldsm4(al[1], aLoB + pa + aOff1);
        #pragma unroll
        for (int g = 0; g < NGRP; g++) ldsm4(bh4[g], bHiB + pb + bOff[g]);
        if constexpr (NT == 64) {
            #pragma unroll
            for (int g = 0; g < NGRP; g++) ldsm4(bl4[g], bLoB + pb + bOff[g]);
        }

        if (c + 1 < nc) {
            int b1 = (c + 1) & 1;
            cvt_store8(sAhi + b1*(128*SR), sAlo + b1*(128*SR), aoff, av0, av1);
            if (NT == 128) cvt_store8(sBhi + b1*(NT*SR), sBlo + b1*(NT*SR), boff, bv0, bv1);
            else           cvt_store4(sBhi + b1*(NT*SR), sBlo + b1*(NT*SR), boff, bv0);
            if (c + 2 < nc) {
                av0 = *(const float4*)(aG + (long)(c+2)*astep);
                av1 = *(const float4*)(aG + (long)(c+2)*astep + a2);
                if (NT == 128) { bv0 = *(const float4*)(bG + (c+2)*16);
                                 bv1 = *(const float4*)(bG + (c+2)*16 + 4); }
                else           { bv0 = *(const float4*)(bG + (c+2)*16); }
            }
        }

        #pragma unroll
        for (int mf = 0; mf < 2; mf++)
            #pragma unroll
            for (int g = 0; g < NGRP; g++) {
                mma16816(acc[mf][g*2+0], ah[mf], &bh4[g][0]);
                mma16816(acc[mf][g*2+1], ah[mf], &bh4[g][2]);
            }
        #pragma unroll
        for (int mf = 0; mf < 2; mf++)
            #pragma unroll
            for (int g = 0; g < NGRP; g++) {
                mma16816(acc[mf][g*2+0], al[mf], &bh4[g][0]);
                mma16816(acc[mf][g*2+1], al[mf], &bh4[g][2]);
            }
        if constexpr (NT == 64) {
            #pragma unroll
            for (int mf = 0; mf < 2; mf++)
                #pragma unroll
                for (int g = 0; g < NGRP; g++) {
                    mma16816(acc[mf][g*2+0], ah[mf], &bl4[g][0]);
                    mma16816(acc[mf][g*2+1], ah[mf], &bl4[g][2]);
                }
        } else {
            #pragma unroll
            for (int g = 0; g < NGRP; g++) ldsm4(bh4[g], bLoB + pb + bOff[g]);
            #pragma unroll
            for (int mf = 0; mf < 2; mf++)
                #pragma unroll
                for (int g = 0; g < NGRP; g++) {
                    mma16816(acc[mf][g*2+0], ah[mf], &bh4[g][0]);
                    mma16816(acc[mf][g*2+1], ah[mf], &bh4[g][2]);
                }
        }
    }

    int r0 = m0 + wm + (lane >> 2);
    int nb = n0 + wn + (lane & 3) * 2;
    #pragma unroll
    for (int mf = 0; mf < 2; mf++) {
        int r = r0 + mf * 16;
        #pragma unroll
        for (int nf = 0; nf < 2*NGRP; nf++) {
            int n = nb + nf * 8;
            float* d = acc[mf][nf];
            if (csel <= 1) {
                float* C = csel == 0 ? g_tok : g_qkv;
                int ldc = (csel == 1) ? 768 : 256;
                float b0 = __ldg(&bias[n]), b1 = __ldg(&bias[n+1]);
                float2 lo2 = {d[0] + b0, d[1] + b1};
                float2 hi2 = {d[2] + b0, d[3] + b1};
                *(float2*)&C[(long)r * ldc + n]       = lo2;
                *(float2*)&C[(long)(r + 8) * ldc + n] = hi2;
            } else if (csel == 4) {
                float2 lo2 = {d[0], d[1]};
                float2 hi2 = {d[2], d[3]};
                *(float2*)&g_wf[(long)r * 256 + n]       = lo2;
                *(float2*)&g_wf[(long)(r + 8) * 256 + n] = hi2;
            } else {
                int o = n >> 4, p = (n >> 2) & 3, q = n & 3;
                float b0 = g_bf[n], b1 = g_bf[n + 1];
                int bb = r >> 10, hp = (r >> 5) & 31, wp = r & 31;
                float2 lo2 = {d[0] + b0, d[1] + b1};
                *(float2*)&yout[((long)(bb*256 + o)*128 + hp*4 + p)*128 + wp*4 + q] = lo2;
                int r8 = r + 8;
                int b2 = r8 >> 10, hp2 = (r8 >> 5) & 31, wp2 = r8 & 31;
                float2 hi2 = {d[2] + b0, d[3] + b1};
                *(float2*)&yout[((long)(b2*256 + o)*128 + hp2*4 + p)*128 + wp2*4 + q] = hi2;
            }
        }
    }
}

// ================= tensor-core flash attention (R11/R14 verbatim) =================
__global__ __launch_bounds__(256, 2)
void attn_mma_kernel() {
    __shared__ __align__(16) uint16_t sKhi[2*2560];
    __shared__ __align__(16) uint16_t sKlo[2*2560];
    __shared__ __align__(16) uint16_t sVhi[2*2560];
    __shared__ __align__(16) uint16_t sVlo[2*2560];

    int tid = threadIdx.x, w = tid >> 5, lane = tid & 31;
    int bx = blockIdx.x, qs = bx & 7, bh = bx >> 3;
    int b = bh >> 3, h = bh & 7;
    int q0 = qs * 128;
    uint32_t kHB = smem_u32(sKhi), kLB = smem_u32(sKlo);
    uint32_t vHB = smem_u32(sVhi), vLB = smem_u32(sVlo);

    int kvrow = tid >> 2, kvdg = (tid & 3) * 8;
    const float* kv0 = &g_qkv[((b << 10) + kvrow) * 768 + h * 32 + kvdg];
    float4 ka = *(const float4*)(kv0 + 256);
    float4 kb = *(const float4*)(kv0 + 260);
    float4 va = *(const float4*)(kv0 + 512);
    float4 vb = *(const float4*)(kv0 + 516);

    {
        int row = tid >> 1;
        const float* qp = &g_qkv[((b << 10) + q0 + row) * 768 + h * 32];
        #pragma unroll
        for (int it = 0; it < 2; it++) {
            int d0 = (tid & 1) * 8 + it * 16;
            float4 v0 = *(const float4*)(qp + d0);
            float4 v1 = *(const float4*)(qp + d0 + 4);
            const float S = 0.17677669529663687f;
            v0.x *= S; v0.y *= S; v0.z *= S; v0.w *= S;
            v1.x *= S; v1.y *= S; v1.z *= S; v1.w *= S;
            cvt_store8(sKhi, sKlo, row * 40 + d0, v0, v1);
        }
    }
    __syncthreads();
    uint32_t qh[2][4], ql[2][4];
    {
        uint32_t qa = ((w * 16 + (lane & 15)) * 40 + (lane >> 4) * 8) * 2;
        #pragma unroll
        for (int dc = 0; dc < 2; dc++) {
            ldsm4(qh[dc], kHB + qa + dc * 32);
            ldsm4(ql[dc], kLB + qa + dc * 32);
        }
    }
    __syncthreads();

    int soff = kvrow * 40 + kvdg;
    cvt_store8(sKhi, sKlo, soff, ka, kb);
    cvt_store8(sVhi, sVlo, soff, va, vb);
    ka = *(const float4*)(kv0 + 49152 + 256);
    kb = *(const float4*)(kv0 + 49152 + 260);
    va = *(const float4*)(kv0 + 49152 + 512);
    vb = *(const float4*)(kv0 + 49152 + 516);

    uint32_t kOff = (((lane & 7) + ((lane >> 4) << 3)) * 40 + (lane & 8)) * 2;
    uint32_t vOff = ((lane & 15) * 40 + (lane >> 4) * 8) * 2;

    int nq0 = q0 + w * 16 + (lane >> 2), nq1 = nq0 + 8;
    int bi0 = ((nq0 >> 5) + 31) * 63 + (nq0 & 31) + 31;
    int bi1 = ((nq1 >> 5) + 31) * 63 + (nq1 & 31) + 31;
    const float* tab = g_table + h * TBL;

    float m0r = -1e30f, m1r = -1e30f, l0 = 0.0f, l1 = 0.0f;
    float O[4][4] = {};

    for (int t = 0; t < 16; t++) {
        __syncthreads();
        uint32_t pk = (t & 1) * 5120;

        float sc[8][4] = {};
        #pragma unroll
        for (int dc = 0; dc < 2; dc++) {
            #pragma unroll
            for (int nfp = 0; nfp < 4; nfp++) {
                uint32_t off = (nfp * 640 + dc * 16) * 2;
                uint32_t b4[4];
                ldsm4(b4, kHB + pk + kOff + off);
                mma16816(sc[2*nfp],   qh[dc], &b4[0]);
                mma16816(sc[2*nfp+1], qh[dc], &b4[2]);
                mma16816(sc[2*nfp],   ql[dc], &b4[0]);
                mma16816(sc[2*nfp+1], ql[dc], &b4[2]);
                ldsm4(b4, kLB + pk + kOff + off);
                mma16816(sc[2*nfp],   qh[dc], &b4[0]);
                mma16816(sc[2*nfp+1], qh[dc], &b4[2]);
            }
        }

        if (t + 1 < 16) {
            int d = ((t + 1) & 1) * 2560 + soff;
            cvt_store8(sKhi, sKlo, d, ka, kb);
            cvt_store8(sVhi, sVlo, d, va, vb);
            if (t + 2 < 16) {
                const float* s = kv0 + (long)(t + 2) * 49152;
                ka = *(const float4*)(s + 256);
                kb = *(const float4*)(s + 260);
                va = *(const float4*)(s + 512);
                vb = *(const float4*)(s + 516);
            }
        }

        int tb = t * 126;
        #pragma unroll
        for (int nf = 0; nf < 8; nf++) {
            int cb = (nf >> 2) * 63 + (nf & 3) * 8 + (lane & 3) * 2;
            sc[nf][0] += __ldg(&tab[bi0 - tb - cb]);
            sc[nf][1] += __ldg(&tab[bi0 - tb - cb - 1]);
            sc[nf][2] += __ldg(&tab[bi1 - tb - cb]);
            sc[nf][3] += __ldg(&tab[bi1 - tb - cb - 1]);
        }

        float mx0 = -1e30f, mx1 = -1e30f;
        #pragma unroll
        for (int nf = 0; nf < 8; nf++) {
            mx0 = fmaxf(mx0, fmaxf(sc[nf][0], sc[nf][1]));
            mx1 = fmaxf(mx1, fmaxf(sc[nf][2], sc[nf][3]));
        }
        #pragma unroll
        for (int off = 1; off < 4; off <<= 1) {
            mx0 = fmaxf(mx0, __shfl_xor_sync(0xffffffffu, mx0, off));
            mx1 = fmaxf(mx1, __shfl_xor_sync(0xffffffffu, mx1, off));
        }
        float mn0 = fmaxf(m0r, mx0), mn1 = fmaxf(m1r, mx1);
        float s0 = __expf(m0r - mn0), s1 = __expf(m1r - mn1);
        m0r = mn0; m1r = mn1;

        float ps0 = 0.0f, ps1 = 0.0f;
        #pragma unroll
        for (int nf = 0; nf < 8; nf++) {
            float p0 = __expf(sc[nf][0] - mn0);
            float p1 = __expf(sc[nf][1] - mn0);
            float p2 = __expf(sc[nf][2] - mn1);
            float p3 = __expf(sc[nf][3] - mn1);
            ps0 += p0 + p1; ps1 += p2 + p3;
            sc[nf][0] = p0; sc[nf][1] = p1; sc[nf][2] = p2; sc[nf][3] = p3;
        }
        #pragma unroll
        for (int off = 1; off < 4; off <<= 1) {
            ps0 += __shfl_xor_sync(0xffffffffu, ps0, off);
            ps1 += __shfl_xor_sync(0xffffffffu, ps1, off);
        }
        l0 = l0 * s0 + ps0;
        l1 = l1 * s1 + ps1;
        #pragma unroll
        for (int nf = 0; nf < 4; nf++) {
            O[nf][0] *= s0; O[nf][1] *= s0;
            O[nf][2] *= s1; O[nf][3] *= s1;
        }

        #pragma unroll
        for (int kc = 0; kc < 4; kc++) {
            uint32_t ph[4], pl[4];
            pack_hilo(sc[2*kc][0],   sc[2*kc][1],   ph[0], pl[0]);
            pack_hilo(sc[2*kc][2],   sc[2*kc][3],   ph[1], pl[1]);
            pack_hilo(sc[2*kc+1][0], sc[2*kc+1][1], ph[2], pl[2]);
            pack_hilo(sc[2*kc+1][2], sc[2*kc+1][3], ph[3], pl[3]);
            #pragma unroll
            for (int dfp = 0; dfp < 2; dfp++) {
                uint32_t off = (kc * 640 + dfp * 16) * 2;
                uint32_t b4[4];
                ldsm4t(b4, vHB + pk + vOff + off);
                mma16816(O[2*dfp],   ph, &b4[0]);
                mma16816(O[2*dfp+1], ph, &b4[2]);
                mma16816(O[2*dfp],   pl, &b4[0]);
                mma16816(O[2*dfp+1], pl, &b4[2]);
                ldsm4t(b4, vLB + pk + vOff + off);
                mma16816(O[2*dfp],   ph, &b4[0]);
                mma16816(O[2*dfp+1], ph, &b4[2]);
            }
        }
    }

    float i0 = 1.0f / l0, i1 = 1.0f / l1;
    #pragma unroll
    for (int nf = 0; nf < 4; nf++) {
        int d = h * 32 + nf * 8 + (lane & 3) * 2;
        float2 o0 = {O[nf][0] * i0, O[nf][1] * i0};
        float2 o1 = {O[nf][2] * i1, O[nf][3] * i1};
        *(float2*)&g_att[((b << 10) + nq0) * 256 + d] = o0;
        *(float2*)&g_att[((b << 10) + nq1) * 256 + d] = o1;
    }
}

// ---------------- launch ----------------
extern "C" void kernel_launch(void* const* d_in, const int* in_sizes, int n_in,
                              void* d_out, int out_size) {
    const float* x         = (const float*)d_in[0];
    const float* w_embed   = (const float*)d_in[1];
    const float* b_embed   = (const float*)d_in[2];
    const float* cpb_w1    = (const float*)d_in[3];
    const float* cpb_b1    = (const float*)d_in[4];
    const float* cpb_w2    = (const float*)d_in[5];
    const float* w_qkv     = (const float*)d_in[6];
    const float* b_qkv     = (const float*)d_in[7];
    const float* w_proj    = (const float*)d_in[8];
    const float* b_proj    = (const float*)d_in[9];
    const float* w_unembed = (const float*)d_in[10];
    const float* b_unembed = (const float*)d_in[11];
    float* y = (float*)d_out;

    rpe_kernel<<<TBL, 512>>>(cpb_w1, cpb_b1, cpb_w2);
    wt_kernel <<<dim3(128, 8), dim3(32, 8)>>>(w_unembed);
    wpT_kernel<<<dim3(8, 8),   dim3(32, 8)>>>(w_proj);
    // Wf[n',c] = wt[n'] . wpT[c] : M=4096, N=256, K=256 -> g_wf
    mma_gemm<64> <<<dim3(4, 32),  256>>>(nullptr, nullptr, nullptr, nullptr, 4, 2, 4, 256);
    bf_kernel <<<512, 256>>>(b_proj, b_unembed);
    // embed: gather x, B=w_embed, K=4096 -> g_tok
    mma_gemm<64> <<<dim3(4, 64),  256>>>(x, w_embed, b_embed, nullptr, 0, 0, 0, 4096);
    // qkv: A=g_tok, B=w_qkv, K=256 -> g_qkv  (NT=64: 768 CTAs, better wave quantization)
    mma_gemm<64> <<<dim3(12, 64), 256>>>(nullptr, w_qkv, b_qkv, nullptr, 1, 0, 1, 256);
    attn_mma_kernel<<<512, 256>>>();
    // fused proj+unembed: A=g_att, B=g_wf, K=256 -> scatter y with g_bf
    mma_gemm<128><<<dim3(32, 64), 256>>>(nullptr, nullptr, nullptr, y, 2, 3, 3, 256);
}